// round 14
// baseline (speedup 1.0000x reference)
#include <cuda_runtime.h>
#include <cstdint>

#define T_LEN 1024
#define NCH   64          // 64 chunks of 16 timesteps (8 float4 per row)

struct Pr {
    float INSC, SMSC, SUB10, CRAK10, RecK, kGW, inv10, cexp2, lgC, argC;
};

__device__ __forceinline__ float ex2f(float x) {
    float r; asm("ex2.approx.ftz.f32 %0, %1;" : "=f"(r) : "f"(x)); return r;
}

__device__ __forceinline__ void cp16(uint32_t smem_dst, const void* gsrc) {
    asm volatile("cp.async.ca.shared.global [%0], [%1], 16;"
                 :: "r"(smem_dst), "l"(gsrc));
}

// One scan step. State: arg = fma(SMSc, cexp2, lgC) (pre-evaluated exp input),
// tf = 10*SMSc/SMSC, ns = SMSc (clipped), GW. COEFF folded into the exponent;
// the SMSC clip deferred via monotonicity (cexp2 <= 0, inv10 > 0).
// Returns Q[t] for the state ENTERING the step (reference's roll(1)).
__device__ __forceinline__ float stepQ(float Prec, float PET,
                                       float& arg, float& tf, float& ns,
                                       float& GW, const Pr& p)
{
    float cap  = ex2f(arg);                      // COEFF * exp(-SQ*frac)
    float INT  = fminf(fminf(p.INSC, PET), Prec);
    float INR  = Prec - INT;
    float POT  = PET - INT;
    float ETS  = fminf(POT, tf);
    float a1   = fmaf(-p.SUB10,  tf, 1.0f);      // 1 - SUB*frac
    float a2   = fmaf(-p.CRAK10, tf, 1.0f);      // 1 - CRAK*frac
    float g    = a1 * a2;
    float base = ns - ETS;
    float RMO  = fminf(INR, cap);                // heaviside blend == min
    float s    = fmaf(RMO, g, base);             // next SMS (pre-clip)
    float h    = RMO * a1;                       // RMO - SRUN
    float ns2  = fminf(s, p.SMSC);
    float RECn = h + (base - ns2);               // REC + overflow (s cancels)
    float Q    = fmaf(p.RecK, GW, INR - h);      // (IRUN+SRUN) + BAS
    GW  = fmaf(p.kGW, GW, RECn);                 // GW*(1-RecK) + RECn
    arg = fmaxf(fmaf(s, p.cexp2, p.lgC), p.argC);
    tf  = fminf(s * p.inv10, 10.0f);
    ns  = ns2;
    return Q;
}

__global__ void __launch_bounds__(32)
hirnn_kernel(const float* __restrict__ in, float* __restrict__ out,
             const float* __restrict__ pINSC, const float* __restrict__ pCOEFF,
             const float* __restrict__ pSQ,   const float* __restrict__ pSMSC,
             const float* __restrict__ pSUB,  const float* __restrict__ pCRAK,
             const float* __restrict__ pRecK, int B)
{
    // Input ring: [slot][row][slice], slice padded 8->9 float4 (conflict-free
    // for both the cooperative cp.async stores and per-thread LDS.128 reads).
    __shared__ float4 sb[4][32][9];
    // Output stage: [buf][row][slice], slice padded 4->5 float4 (conflict-free
    // for per-thread STS.128 and the cooperative LDS.128 read-out).
    __shared__ float4 so[2][32][5];

    int t = threadIdx.x;
    int b = blockIdx.x * 32 + t;
    bool active = (b < B);
    int brow = min(b, B - 1);

    Pr p;
    p.INSC      = fminf(fmaxf(pINSC[0]  * 5.0f,   0.5f),   5.0f);
    float COEFF = fminf(fmaxf(pCOEFF[0] * 400.0f, 50.0f),  400.0f);
    float SQ    = fminf(fmaxf(pSQ[0]    * 6.0f,   0.0f),   6.0f);
    p.SMSC      = fminf(fmaxf(pSMSC[0]  * 500.0f, 50.0f),  500.0f);
    float SUB   = fminf(fmaxf(pSUB[0],            0.0f),   1.0f);
    float CRAK  = fminf(fmaxf(pCRAK[0],           0.0f),   1.0f);
    p.RecK      = fminf(fmaxf(pRecK[0]  * 0.3f,   0.003f), 0.3f);
    p.kGW       = 1.0f - p.RecK;
    float invS  = 1.0f / p.SMSC;
    p.inv10     = 10.0f * invS;
    p.SUB10     = SUB  * 0.1f;
    p.CRAK10    = CRAK * 0.1f;
    p.cexp2     = -SQ * invS * 1.44269504088896f; // exp(x)=exp2(x*log2e)
    p.lgC       = __log2f(COEFF);                 // fold COEFF into exponent
    p.argC      = fmaf(p.SMSC, p.cexp2, p.lgC);   // arg at s >= SMSC

    // Cooperative coalesced input: lane l fetches 16B slice (l&7) of row
    // warp0 + 4k + (l>>3); each cp.async covers 4 contiguous 128B lines.
    const char* inb = (const char*)in;
    int warp0 = blockIdx.x * 32;
    int rsel  = t >> 3;
    int ssel  = t & 7;

    const char* gp[8];
    uint32_t    sp[8];
    #pragma unroll
    for (int k = 0; k < 8; ++k) {
        int row = min(warp0 + 4 * k + rsel, B - 1);
        gp[k] = inb + (size_t)row * (2 * T_LEN * 4) + ssel * 16;
        sp[k] = (uint32_t)__cvta_generic_to_shared(&sb[0][4 * k + rsel][ssel]);
    }
    const uint32_t SLOT = sizeof(float4) * 32 * 9;   // bytes per input slot

    // Cooperative coalesced output: instr i, lane l stores slice (l>>3) of
    // row 8i + (l&7): 64B contiguous per row, 8 lines per STG instruction.
    char* obase = (char*)out + (size_t)(warp0 + (t & 7)) * (T_LEN * 4)
                + (t >> 3) * 16;
    bool pv[4];
    #pragma unroll
    for (int i = 0; i < 4; ++i)
        pv[i] = (warp0 + 8 * i + (t & 7)) < B;

    float arg = p.lgC, tf = 0.0f, ns = 0.0f, GW = 0.0f;

    // Prologue: chunks 0..2 (pipeline distance 3 => ~48 steps of cover).
    #pragma unroll
    for (int c0 = 0; c0 < 3; ++c0) {
        #pragma unroll
        for (int k = 0; k < 8; ++k)
            cp16(sp[k] + c0 * SLOT, gp[k] + c0 * 128);
        asm volatile("cp.async.commit_group;");
    }

    #pragma unroll 1
    for (int c = 0; c < NCH; ++c) {
        // Issue chunk c+3 into slot (c+3)&3 (reads use slot c&3 — disjoint).
        // Tail re-issues the last chunk into dead slots: harmless, in-bounds.
        int cn = min(c + 3, NCH - 1);
        uint32_t sof = ((c + 3) & 3) * SLOT;
        #pragma unroll
        for (int k = 0; k < 8; ++k)
            cp16(sp[k] + sof, gp[k] + cn * 128);
        asm volatile("cp.async.commit_group;");

        // Chunk c complete when <= 3 groups remain in flight.
        asm volatile("cp.async.wait_group 3;");

        int s4 = c & 3;
        int ob = c & 1;
        #pragma unroll
        for (int q = 0; q < 4; ++q) {
            float4 A = sb[s4][t][2 * q];
            float4 C = sb[s4][t][2 * q + 1];
            float4 r;
            r.x = stepQ(A.x, A.y, arg, tf, ns, GW, p);
            r.y = stepQ(A.z, A.w, arg, tf, ns, GW, p);
            r.z = stepQ(C.x, C.y, arg, tf, ns, GW, p);
            r.w = stepQ(C.z, C.w, arg, tf, ns, GW, p);
            so[ob][t][q] = r;
        }
        __syncwarp();
        // Cooperative coalesced store of this chunk's 32 rows x 64B.
        #pragma unroll
        for (int i = 0; i < 4; ++i) {
            float4 v = so[ob][8 * i + (t & 7)][t >> 3];
            if (pv[i])
                *reinterpret_cast<float4*>(obase + i * 8 * (T_LEN * 4) + c * 64) = v;
        }
        // Next chunk writes the other 'so' buffer; the WAR distance (2 chunks)
        // is covered by the next iteration's __syncwarp().
    }

    // Q[0]: roll wraps the FINAL state to t=0 — one extra step, t=0 inputs.
    float2 x0 = *reinterpret_cast<const float2*>(inb + (size_t)brow * (2 * T_LEN * 4));
    float q0 = stepQ(x0.x, x0.y, arg, tf, ns, GW, p);
    if (active) out[(size_t)b * T_LEN] = q0;
}

extern "C" void kernel_launch(void* const* d_in, const int* in_sizes, int n_in,
                              void* d_out, int out_size)
{
    const float* in = (const float*)d_in[0];
    int B = in_sizes[0] / (2 * T_LEN);
    int block = 32;                       // 1 warp/block -> ~all SMs, no sharing
    int grid  = (B + block - 1) / block;
    hirnn_kernel<<<grid, block>>>(in, (float*)d_out,
                                  (const float*)d_in[1], (const float*)d_in[2],
                                  (const float*)d_in[3], (const float*)d_in[4],
                                  (const float*)d_in[5], (const float*)d_in[6],
                                  (const float*)d_in[7], B);
}

// round 17
// speedup vs baseline: 1.2043x; 1.2043x over previous
#include <cuda_runtime.h>
#include <cstdint>

#define T_LEN 1024
#define NCH   64          // 64 chunks of 16 timesteps (8 float4 per row)

struct Pr {
    float INSC, SMSC, SUB10, CRAK10, inv10, cexp2, lgC, argC;
    uint64_t N11;   // packed (-1, -1)
    uint64_t RK;    // packed (RecK, 1-RecK)
};

__device__ __forceinline__ float ex2f(float x) {
    float r; asm("ex2.approx.ftz.f32 %0, %1;" : "=f"(r) : "f"(x)); return r;
}

__device__ __forceinline__ void cp16(uint32_t smem_dst, const void* gsrc) {
    asm volatile("cp.async.ca.shared.global [%0], [%1], 16;"
                 :: "r"(smem_dst), "l"(gsrc));
}

// f32x2 packed helpers (Blackwell packed-float pipe; PTX-only, no C++ autofuse)
__device__ __forceinline__ uint64_t pk(float lo, float hi) {
    uint64_t r; asm("mov.b64 %0, {%1, %2};" : "=l"(r) : "f"(lo), "f"(hi));
    return r;
}
__device__ __forceinline__ void upk(uint64_t v, float& lo, float& hi) {
    asm("mov.b64 {%0, %1}, %2;" : "=f"(lo), "=f"(hi) : "l"(v));
}
__device__ __forceinline__ uint64_t fma2(uint64_t a, uint64_t b, uint64_t c) {
    uint64_t r;
    asm("fma.rn.f32x2 %0, %1, %2, %3;" : "=l"(r) : "l"(a), "l"(b), "l"(c));
    return r;
}

// One scan step. State: arg (exp2 input, COEFF folded), ns (clipped SMS),
// GW. The min inside the recurrence distributes over the (negative-slope)
// fma:  fma(min(INR,cap)*g + base, cexp2, lgC) = max(cg*INR+c0, cg*cap+c0),
// which removes RMO->s from the exp dependency cycle.
// Returns Q[t] for the state ENTERING the step (reference's roll(1)).
__device__ __forceinline__ float stepQ(float Prec, float PET,
                                       float& arg, float& ns, float& GW,
                                       const Pr& p)
{
    float cap  = ex2f(arg);                         // MUFU, issue first
    float INT  = fminf(fminf(p.INSC, PET), Prec);
    // (INR, POT) = (Prec, PET) - (INT, INT)  via packed FFMA2
    uint64_t ip2 = fma2(pk(INT, INT), p.N11, pk(Prec, PET));
    float INR, POT; upk(ip2, INR, POT);
    float tf   = ns * p.inv10;                      // 10*SMSc/SMSC
    float a1   = fmaf(-p.SUB10,  tf, 1.0f);         // 1 - SUB*frac
    float a2   = fmaf(-p.CRAK10, tf, 1.0f);         // 1 - CRAK*frac
    float ETS  = fminf(POT, tf);
    float base = ns - ETS;
    float g    = a1 * a2;
    float cg   = g * p.cexp2;                       // <= 0
    float c0   = fmaf(p.cexp2, base, p.lgC);
    float tA   = fmaf(cg, INR, c0);                 // RMO=INR branch
    float RMO  = fminf(INR, cap);                   // heaviside blend == min
    float tB   = fmaf(cg, cap, c0);                 // RMO=cap branch (chain)
    arg        = fmaxf(fmaxf(tB, p.argC), tA);      // next exp2 input
    float s    = fmaf(RMO, g, base);                // next SMS (pre-clip)
    float ns2  = fminf(s, p.SMSC);
    float d    = base - ns2;
    float qp   = fmaf(-RMO, a1, INR);               // INR - (RMO - SRUN)
    float RECn = fmaf(RMO, a1, d);                  // REC + overflow
    // (Q, GW') = (RecK, kGW) * (GW, GW) + (qp, RECn)  via packed FFMA2
    uint64_t qg = fma2(p.RK, pk(GW, GW), pk(qp, RECn));
    float Q; upk(qg, Q, GW);
    ns = ns2;
    return Q;
}

__global__ void __launch_bounds__(32)
hirnn_kernel(const float* __restrict__ in, float* __restrict__ out,
             const float* __restrict__ pINSC, const float* __restrict__ pCOEFF,
             const float* __restrict__ pSQ,   const float* __restrict__ pSMSC,
             const float* __restrict__ pSUB,  const float* __restrict__ pCRAK,
             const float* __restrict__ pRecK, int B)
{
    // [slot][row][slice], slice padded 8->9 float4: conflict-free for both
    // the cooperative cp.async stores and per-thread LDS.128 reads.
    __shared__ float4 sb[4][32][9];

    int t = threadIdx.x;
    int b = blockIdx.x * 32 + t;
    bool active = (b < B);
    int brow = min(b, B - 1);

    Pr p;
    p.INSC      = fminf(fmaxf(pINSC[0]  * 5.0f,   0.5f),   5.0f);
    float COEFF = fminf(fmaxf(pCOEFF[0] * 400.0f, 50.0f),  400.0f);
    float SQ    = fminf(fmaxf(pSQ[0]    * 6.0f,   0.0f),   6.0f);
    p.SMSC      = fminf(fmaxf(pSMSC[0]  * 500.0f, 50.0f),  500.0f);
    float SUB   = fminf(fmaxf(pSUB[0],            0.0f),   1.0f);
    float CRAK  = fminf(fmaxf(pCRAK[0],           0.0f),   1.0f);
    float RecK  = fminf(fmaxf(pRecK[0]  * 0.3f,   0.003f), 0.3f);
    float invS  = 1.0f / p.SMSC;
    p.inv10     = 10.0f * invS;
    p.SUB10     = SUB  * 0.1f;
    p.CRAK10    = CRAK * 0.1f;
    p.cexp2     = -SQ * invS * 1.44269504088896f; // exp(x)=exp2(x*log2e)
    p.lgC       = __log2f(COEFF);                 // fold COEFF into exponent
    p.argC      = fmaf(p.SMSC, p.cexp2, p.lgC);   // arg at s >= SMSC
    p.N11       = pk(-1.0f, -1.0f);
    p.RK        = pk(RecK, 1.0f - RecK);

    // Cooperative coalesced input: lane l fetches 16B slice (l&7) of row
    // warp0 + 4k + (l>>3); each cp.async covers 4 contiguous 128B lines.
    const char* inb = (const char*)in;
    int warp0 = blockIdx.x * 32;
    int rsel  = t >> 3;
    int ssel  = t & 7;

    const char* gp[8];
    uint32_t    sp[8];
    #pragma unroll
    for (int k = 0; k < 8; ++k) {
        int row = min(warp0 + 4 * k + rsel, B - 1);
        gp[k] = inb + (size_t)row * (2 * T_LEN * 4) + ssel * 16;
        sp[k] = (uint32_t)__cvta_generic_to_shared(&sb[0][4 * k + rsel][ssel]);
    }
    const uint32_t SLOT = sizeof(float4) * 32 * 9;   // bytes per input slot

    float4* qo = reinterpret_cast<float4*>(out + (size_t)brow * T_LEN);

    float arg = p.lgC, ns = 0.0f, GW = 0.0f;

    // Prologue: chunks 0 and 1 (pipeline distance 2 => ~32 steps of cover).
    #pragma unroll
    for (int c0i = 0; c0i < 2; ++c0i) {
        #pragma unroll
        for (int k = 0; k < 8; ++k)
            cp16(sp[k] + c0i * SLOT, gp[k] + c0i * 128);
        asm volatile("cp.async.commit_group;");
    }

    #pragma unroll 1
    for (int c = 0; c < NCH; ++c) {
        // Issue chunk c+2 into slot (c+2)&3; tail re-issues the last chunk
        // into dead slots (never read again) — harmless, in-bounds.
        int cn = min(c + 2, NCH - 1);
        uint32_t sof = ((c + 2) & 3) * SLOT;
        #pragma unroll
        for (int k = 0; k < 8; ++k)
            cp16(sp[k] + sof, gp[k] + cn * 128);
        asm volatile("cp.async.commit_group;");

        // Chunk c complete when <= 2 groups remain in flight. Single warp,
        // LSU-ordered LDGSTS: no barrier needed.
        asm volatile("cp.async.wait_group 2;");

        int s4 = c & 3;
        #pragma unroll
        for (int q = 0; q < 4; ++q) {
            float4 A = sb[s4][t][2 * q];
            float4 C = sb[s4][t][2 * q + 1];
            float4 r;
            r.x = stepQ(A.x, A.y, arg, ns, GW, p);
            r.y = stepQ(A.z, A.w, arg, ns, GW, p);
            r.z = stepQ(C.x, C.y, arg, ns, GW, p);
            r.w = stepQ(C.z, C.w, arg, ns, GW, p);
            if (active) qo[c * 4 + q] = r;
        }
    }

    // Q[0]: roll wraps the FINAL state to t=0 — one extra step, t=0 inputs.
    float2 x0 = *reinterpret_cast<const float2*>(inb + (size_t)brow * (2 * T_LEN * 4));
    float q0 = stepQ(x0.x, x0.y, arg, ns, GW, p);
    if (active) out[(size_t)b * T_LEN] = q0;
}

extern "C" void kernel_launch(void* const* d_in, const int* in_sizes, int n_in,
                              void* d_out, int out_size)
{
    const float* in = (const float*)d_in[0];
    int B = in_sizes[0] / (2 * T_LEN);
    int block = 32;                       // 1 warp/block -> ~all SMs, no sharing
    int grid  = (B + block - 1) / block;
    hirnn_kernel<<<grid, block>>>(in, (float*)d_out,
                                  (const float*)d_in[1], (const float*)d_in[2],
                                  (const float*)d_in[3], (const float*)d_in[4],
                                  (const float*)d_in[5], (const float*)d_in[6],
                                  (const float*)d_in[7], B);
}